// round 1
// baseline (speedup 1.0000x reference)
#include <cuda_runtime.h>

#define BB 4
#define TT_TOT 1024
#define HW 1296
#define NBINS 512
#define LOOKUP 101
#define OUT_DIM 128

// band kernel tiling
#define TILE_T 32
#define BAND 144
#define ROWPAD 148
#define KC 128
#define NTHR2 288   // 8 t-groups x 36 j-groups
// fc kernel
#define RPB 16

__device__ float g_hist[BB * TT_TOT * NBINS];   // 8 MB normalized histograms
__device__ float g_win[BB * TT_TOT * LOOKUP];   // 1.65 MB banded sims

// ---------------------------------------------------------------------------
// Kernel 1: per-frame 512-bin color histogram + L2 normalize
// ---------------------------------------------------------------------------
__global__ void hist_kernel(const int* __restrict__ frames) {
    __shared__ int hist[NBINS];
    __shared__ float wsum[8];
    const int f = blockIdx.x;           // frame index 0..4095
    const int tid = threadIdx.x;        // 256 threads

    hist[tid] = 0;
    hist[tid + 256] = 0;
    __syncthreads();

    const int* p = frames + (size_t)f * (HW * 3);
    for (int i = tid; i < HW; i += 256) {
        int r = p[3 * i + 0];
        int g = p[3 * i + 1];
        int b = p[3 * i + 2];
        int bin = ((r >> 5) << 6) | ((g >> 5) << 3) | (b >> 5);
        atomicAdd(&hist[bin], 1);
    }
    __syncthreads();

    float h0 = (float)hist[tid];
    float h1 = (float)hist[tid + 256];
    float s = h0 * h0 + h1 * h1;
#pragma unroll
    for (int o = 16; o > 0; o >>= 1) s += __shfl_xor_sync(0xffffffffu, s, o);
    if ((tid & 31) == 0) wsum[tid >> 5] = s;
    __syncthreads();

    float tot = 0.f;
#pragma unroll
    for (int w = 0; w < 8; w++) tot += wsum[w];
    // tot >= HW^2/NBINS > 0 always (1296 pixels), so rsqrt is safe
    float rn = rsqrtf(tot);

    float* o = g_hist + (size_t)f * NBINS;
    o[tid] = h0 * rn;
    o[tid + 256] = h1 * rn;
}

// ---------------------------------------------------------------------------
// Kernel 2: banded self-similarity.
// Block = 32 consecutive t of one batch. Computes the dense 32x144 rectangle
// (covers the needed 101-wide window) via register-tiled fp32 GEMM over K=512.
// smem holds the K-chunk TRANSPOSED: sm[k][row] so x-reads broadcast and
// y-reads are contiguous float4.
// ---------------------------------------------------------------------------
__global__ void band_kernel(void) {
    extern __shared__ __align__(16) float sm[];   // [KC][ROWPAD]

    const int blk = blockIdx.x;              // 0..127
    const int b = blk >> 5;                  // batch
    const int tb = (blk & 31) * TILE_T;      // t0
    const int tid = threadIdx.x;             // 0..287
    const int tg = tid / 36;                 // t-group 0..7 (4 t's each)
    const int jg = tid - tg * 36;            // j-group 0..35 (4 rows each)

    const float* hb = g_hist + (size_t)b * (TT_TOT * NBINS);
    const int j0 = tb - 52;                  // band row r -> t index j0+r

    float acc[4][4];
#pragma unroll
    for (int i = 0; i < 4; i++)
#pragma unroll
        for (int u = 0; u < 4; u++) acc[i][u] = 0.f;

    for (int kc = 0; kc < NBINS / KC; ++kc) {
        __syncthreads();
        // load 144 rows x 128 k, transposed, zero-fill out-of-range rows
        for (int e = tid; e < BAND * KC; e += NTHR2) {
            int r = e >> 7;                  // / KC
            int k = e & (KC - 1);
            int j = j0 + r;
            float v = 0.f;
            if ((unsigned)j < (unsigned)TT_TOT)
                v = hb[j * NBINS + kc * KC + k];
            sm[k * ROWPAD + r] = v;
        }
        __syncthreads();

#pragma unroll 4
        for (int k = 0; k < KC; ++k) {
            const float* row = sm + k * ROWPAD;
            float4 xv = *(const float4*)(row + 52 + 4 * tg);  // 4 t rows
            float4 yv = *(const float4*)(row + 4 * jg);       // 4 j rows
            acc[0][0] += xv.x * yv.x; acc[0][1] += xv.x * yv.y;
            acc[0][2] += xv.x * yv.z; acc[0][3] += xv.x * yv.w;
            acc[1][0] += xv.y * yv.x; acc[1][1] += xv.y * yv.y;
            acc[1][2] += xv.y * yv.z; acc[1][3] += xv.y * yv.w;
            acc[2][0] += xv.z * yv.x; acc[2][1] += xv.z * yv.y;
            acc[2][2] += xv.z * yv.z; acc[2][3] += xv.z * yv.w;
            acc[3][0] += xv.w * yv.x; acc[3][1] += xv.w * yv.y;
            acc[3][2] += xv.w * yv.z; acc[3][3] += xv.w * yv.w;
        }
    }

    // scatter valid window entries: l = r - (t - t0) - 2
#pragma unroll
    for (int i = 0; i < 4; ++i) {
        int d = 4 * tg + i;                  // t - t0
        int t = tb + d;
        float* wr = g_win + ((size_t)(b * TT_TOT + t)) * LOOKUP;
#pragma unroll
        for (int u = 0; u < 4; ++u) {
            int l = 4 * jg + u - d - 2;
            if ((unsigned)l < (unsigned)LOOKUP) wr[l] = acc[i][u];
        }
    }
}

// ---------------------------------------------------------------------------
// Kernel 3: out[bt, o] = relu(win[bt, :] @ W[:, o] + b[o])
// Block: 128 threads (o = tid), 16 bt-rows per block. W cached in smem.
// ---------------------------------------------------------------------------
__global__ void fc_kernel(const float* __restrict__ fcw,
                          const float* __restrict__ fcb,
                          float* __restrict__ out) {
    extern __shared__ __align__(16) float sw[];   // LOOKUP*OUT_DIM
    __shared__ float swin[RPB][LOOKUP + 3];

    const int tid = threadIdx.x;    // 128
    const int bt0 = blockIdx.x * RPB;

    for (int e = tid; e < LOOKUP * OUT_DIM; e += 128) sw[e] = fcw[e];
    for (int e = tid; e < RPB * LOOKUP; e += 128) {
        int row = e / LOOKUP;
        int l = e - row * LOOKUP;
        swin[row][l] = g_win[(size_t)(bt0 + row) * LOOKUP + l];
    }
    __syncthreads();

    float acc[RPB];
    float bias = fcb[tid];
#pragma unroll
    for (int r = 0; r < RPB; ++r) acc[r] = bias;

#pragma unroll 4
    for (int l = 0; l < LOOKUP; ++l) {
        float wv = sw[l * OUT_DIM + tid];
#pragma unroll
        for (int r = 0; r < RPB; ++r) acc[r] += swin[r][l] * wv;
    }

#pragma unroll
    for (int r = 0; r < RPB; ++r)
        out[(size_t)(bt0 + r) * OUT_DIM + tid] = fmaxf(acc[r], 0.f);
}

// ---------------------------------------------------------------------------
extern "C" void kernel_launch(void* const* d_in, const int* in_sizes, int n_in,
                              void* d_out, int out_size) {
    const int* frames = (const int*)d_in[0];
    const float* fcw = (const float*)d_in[1];
    const float* fcb = (const float*)d_in[2];
    float* out = (float*)d_out;

    // >48KB dynamic smem opt-in (idempotent, not a stream op: capture-safe)
    cudaFuncSetAttribute(band_kernel, cudaFuncAttributeMaxDynamicSharedMemorySize,
                         KC * ROWPAD * (int)sizeof(float));
    cudaFuncSetAttribute(fc_kernel, cudaFuncAttributeMaxDynamicSharedMemorySize,
                         LOOKUP * OUT_DIM * (int)sizeof(float));

    hist_kernel<<<BB * TT_TOT, 256>>>(frames);
    band_kernel<<<(BB * TT_TOT) / TILE_T, NTHR2, KC * ROWPAD * sizeof(float)>>>();
    fc_kernel<<<(BB * TT_TOT) / RPB, 128, LOOKUP * OUT_DIM * sizeof(float)>>>(fcw, fcb, out);
}

// round 6
// speedup vs baseline: 1.2230x; 1.2230x over previous
#include <cuda_runtime.h>

#define BB 4
#define TT_TOT 1024
#define HW 1296
#define NBINS 512
#define LOOKUP 101
#define OUT_DIM 128

// band kernel tiling
#define TILE_T 32
#define BAND 132           // j range [tb-50, tb+81], r = j - (tb-50) in [0,131]
#define RP 136             // floats per k-row in smem (34 granules of 16B)
#define KC 128             // k chunk
#define KSPLIT 2
#define NTHR2 224          // 7 full warps; compute uses tid<208 (8 tg x 26 jg)
#define NCOMP 208
#define TOTW (BB * TT_TOT * LOOKUP)
// fc kernel
#define RPB 16

__device__ float g_hist[BB * TT_TOT * NBINS];       // 8 MB normalized histograms
__device__ float g_win[KSPLIT * BB * TT_TOT * LOOKUP]; // 2 partial banded sims

// ---------------------------------------------------------------------------
// Kernel 1: per-frame 512-bin color histogram + L2 normalize.
// int4 loads (4 pixels / 3 loads), dual bank-staggered hist copies.
// ---------------------------------------------------------------------------
__global__ void hist_kernel(const int* __restrict__ frames) {
    __shared__ int hists[2 * 520];   // copy c at c*520; 520 ints -> +8 bank stagger
    __shared__ float wsum[8];
    const int f = blockIdx.x;
    const int tid = threadIdx.x;     // 256

    for (int i = tid; i < 2 * 520; i += 256) hists[i] = 0;
    __syncthreads();

    const int4* p = (const int4*)frames + (size_t)f * (HW * 3 / 4);
    int* myh = hists + (tid & 1) * 520;

    // 324 quads of 4 pixels
    for (int q = tid; q < HW / 4; q += 256) {
        int4 a = p[3 * q + 0];
        int4 b = p[3 * q + 1];
        int4 c = p[3 * q + 2];
        int b0 = ((a.x >> 5) << 6) | ((a.y >> 5) << 3) | (a.z >> 5);
        int b1 = ((a.w >> 5) << 6) | ((b.x >> 5) << 3) | (b.y >> 5);
        int b2 = ((b.z >> 5) << 6) | ((b.w >> 5) << 3) | (c.x >> 5);
        int b3 = ((c.y >> 5) << 6) | ((c.z >> 5) << 3) | (c.w >> 5);
        atomicAdd(&myh[b0], 1);
        atomicAdd(&myh[b1], 1);
        atomicAdd(&myh[b2], 1);
        atomicAdd(&myh[b3], 1);
    }
    __syncthreads();

    float h0 = (float)(hists[tid] + hists[520 + tid]);
    float h1 = (float)(hists[tid + 256] + hists[520 + tid + 256]);
    float s = h0 * h0 + h1 * h1;
#pragma unroll
    for (int o = 16; o > 0; o >>= 1) s += __shfl_xor_sync(0xffffffffu, s, o);
    if ((tid & 31) == 0) wsum[tid >> 5] = s;
    __syncthreads();

    float tot = 0.f;
#pragma unroll
    for (int w = 0; w < 8; w++) tot += wsum[w];
    float rn = rsqrtf(tot);   // tot >= HW^2/NBINS > 0

    float* o = g_hist + (size_t)f * NBINS;
    o[tid] = h0 * rn;
    o[tid + 256] = h1 * rn;
}

// ---------------------------------------------------------------------------
// Kernel 2: banded self-similarity, diagonal-staggered 4x4 register tiles.
// Block = (t-tile of 32) x (K half of 256). Thread (tg,jg): t = tb+4tg+i,
// j = tb+4(tg+jg)-50+u, so l = 4jg+u-i. smem holds K-chunk transposed with
// XOR-granule swizzle: phys(k,col) = k*RP + 4*((col>>2) ^ ((k>>2)&7)) + (col&3)
// (unswizzled when col>>2 == 32). Conflict-free STS + float4 LDS + coalesced LDG.
// ---------------------------------------------------------------------------
__global__ void band_kernel(void) {
    extern __shared__ __align__(16) float sm[];   // KC * RP floats

    const int blk = blockIdx.x;              // 0..127
    const int ks = blockIdx.y;               // K half
    const int b = blk >> 5;
    const int tb = (blk & 31) * TILE_T;
    const int tid = threadIdx.x;             // 0..223
    const int warpid = tid >> 5, lane = tid & 31;
    const int roff = lane >> 3, k4off = lane & 7;

    const float* hb = g_hist + (size_t)b * (TT_TOT * NBINS);
    const int j0 = tb - 50;

    // compute-thread decomposition
    const int tg = tid / 26;                 // 0..7 (only valid tid<208)
    const int jg = tid - tg * 26;            // 0..25
    const int gy = tg + jg;                  // y granule (col>>2), 0..32

    float acc[4][4];
#pragma unroll
    for (int i = 0; i < 4; i++)
#pragma unroll
        for (int u = 0; u < 4; u++) acc[i][u] = 0.f;

    for (int kc2 = 0; kc2 < 2; kc2++) {
        const int kb = ks * 256 + kc2 * KC;
        __syncthreads();
        // loader: warp = 4 r x 32 k per iter; 33 r-groups x 4 k-groups = 132 iters
        for (int it = warpid; it < 33 * 4; it += 7) {
            int rg = it >> 2;
            int kg = it & 3;
            int r = rg * 4 + roff;
            int k = kg * 32 + 4 * k4off;
            int j = j0 + r;
            float4 v = make_float4(0.f, 0.f, 0.f, 0.f);
            if ((unsigned)j < (unsigned)TT_TOT)
                v = *(const float4*)(hb + (size_t)j * NBINS + kb + k);
            int sw = (k >> 2) & 7;
            int g = (rg < 32) ? (rg ^ sw) : rg;
            float* dst = sm + k * RP + 4 * g + roff;
            dst[0 * RP] = v.x;
            dst[1 * RP] = v.y;
            dst[2 * RP] = v.z;
            dst[3 * RP] = v.w;
        }
        __syncthreads();

        if (tid < NCOMP) {
#pragma unroll 8
            for (int k4 = 0; k4 < 32; k4++) {
                const int sw = k4 & 7;
                const float* rowb = sm + (k4 * 4) * RP;
                const int yoff = 4 * ((gy < 32) ? (gy ^ sw) : gy);
                const int xaoff = 4 * ((12 + tg) ^ sw) + 2;
                const int xboff = 4 * ((13 + tg) ^ sw);
#pragma unroll
                for (int c = 0; c < 4; c++) {
                    const float* rb = rowb + c * RP;
                    float2 xa = *(const float2*)(rb + xaoff);
                    float2 xb = *(const float2*)(rb + xboff);
                    float4 yv = *(const float4*)(rb + yoff);
                    acc[0][0] += xa.x * yv.x; acc[0][1] += xa.x * yv.y;
                    acc[0][2] += xa.x * yv.z; acc[0][3] += xa.x * yv.w;
                    acc[1][0] += xa.y * yv.x; acc[1][1] += xa.y * yv.y;
                    acc[1][2] += xa.y * yv.z; acc[1][3] += xa.y * yv.w;
                    acc[2][0] += xb.x * yv.x; acc[2][1] += xb.x * yv.y;
                    acc[2][2] += xb.x * yv.z; acc[2][3] += xb.x * yv.w;
                    acc[3][0] += xb.y * yv.x; acc[3][1] += xb.y * yv.y;
                    acc[3][2] += xb.y * yv.z; acc[3][3] += xb.y * yv.w;
                }
            }
        }
    }

    if (tid < NCOMP) {
        float* wpart = g_win + (size_t)ks * TOTW;
#pragma unroll
        for (int i = 0; i < 4; ++i) {
            int t = tb + 4 * tg + i;
            float* wr = wpart + ((size_t)(b * TT_TOT + t)) * LOOKUP;
#pragma unroll
            for (int u = 0; u < 4; ++u) {
                int l = 4 * jg + u - i;
                if ((unsigned)l < (unsigned)LOOKUP) wr[l] = acc[i][u];
            }
        }
    }
}

// ---------------------------------------------------------------------------
// Kernel 3: out[bt, o] = relu((win0+win1)[bt, :] @ W[:, o] + b[o])
// ---------------------------------------------------------------------------
__global__ void fc_kernel(const float* __restrict__ fcw,
                          const float* __restrict__ fcb,
                          float* __restrict__ out) {
    extern __shared__ __align__(16) float swt[];   // LOOKUP*OUT_DIM
    __shared__ float swin[RPB][LOOKUP + 3];

    const int tid = threadIdx.x;    // 128
    const int bt0 = blockIdx.x * RPB;

    for (int e = tid; e < LOOKUP * OUT_DIM; e += 128) swt[e] = fcw[e];
    for (int e = tid; e < RPB * LOOKUP; e += 128) {
        int row = e / LOOKUP;
        int l = e - row * LOOKUP;
        size_t idx = (size_t)(bt0 + row) * LOOKUP + l;
        swin[row][l] = g_win[idx] + g_win[TOTW + idx];
    }
    __syncthreads();

    float acc[RPB];
    float bias = fcb[tid];
#pragma unroll
    for (int r = 0; r < RPB; ++r) acc[r] = bias;

#pragma unroll 4
    for (int l = 0; l < LOOKUP; ++l) {
        float wv = swt[l * OUT_DIM + tid];
#pragma unroll
        for (int r = 0; r < RPB; ++r) acc[r] += swin[r][l] * wv;
    }

#pragma unroll
    for (int r = 0; r < RPB; ++r)
        out[(size_t)(bt0 + r) * OUT_DIM + tid] = fmaxf(acc[r], 0.f);
}

// ---------------------------------------------------------------------------
extern "C" void kernel_launch(void* const* d_in, const int* in_sizes, int n_in,
                              void* d_out, int out_size) {
    const int* frames = (const int*)d_in[0];
    const float* fcw = (const float*)d_in[1];
    const float* fcb = (const float*)d_in[2];
    float* out = (float*)d_out;

    cudaFuncSetAttribute(band_kernel, cudaFuncAttributeMaxDynamicSharedMemorySize,
                         KC * RP * (int)sizeof(float));
    cudaFuncSetAttribute(fc_kernel, cudaFuncAttributeMaxDynamicSharedMemorySize,
                         LOOKUP * OUT_DIM * (int)sizeof(float));

    hist_kernel<<<BB * TT_TOT, 256>>>(frames);
    dim3 bgrid((BB * TT_TOT) / TILE_T, KSPLIT);
    band_kernel<<<bgrid, NTHR2, KC * RP * sizeof(float)>>>();
    fc_kernel<<<(BB * TT_TOT) / RPB, 128, LOOKUP * OUT_DIM * sizeof(float)>>>(fcw, fcb, out);
}

// round 12
// speedup vs baseline: 1.4860x; 1.2151x over previous
#include <cuda_runtime.h>

#define BB 4
#define TT_TOT 1024
#define HW 1296
#define NBINS 512
#define LOOKUP 101
#define OUT_DIM 128
#define TOTW (BB * TT_TOT * LOOKUP)

// band kernel (tf32 mma)
#define BTILE 32
#define BROWS 160          // j in [tb-56, tb+104)
#define SSTRIDE 68         // floats per smem row (64 + 4 pad -> conflict-free frags)
#define KCH 64             // K per stage
#define NSTAGES 8          // 512 / 64
#define STAGE_WORDS (BROWS * SSTRIDE)
// fc kernel
#define RPB 16

__device__ float g_hist[BB * TT_TOT * NBINS];   // 8 MB normalized histograms
__device__ float g_win[TOTW];                   // banded sims

// ---------------------------------------------------------------------------
// Kernel 1: per-frame 512-bin color histogram + L2 normalize.
// ---------------------------------------------------------------------------
__global__ void hist_kernel(const int* __restrict__ frames) {
    __shared__ int hists[4 * 520];   // 4 copies, 520-int stride (8-bank stagger)
    __shared__ float wsum[8];
    const int f = blockIdx.x;
    const int tid = threadIdx.x;     // 256

    for (int i = tid; i < 4 * 520; i += 256) hists[i] = 0;
    __syncthreads();

    const int4* p = (const int4*)frames + (size_t)f * (HW * 3 / 4);
    int* myh = hists + (tid & 3) * 520;

    for (int q = tid; q < HW / 4; q += 256) {
        int4 a = p[3 * q + 0];
        int4 b = p[3 * q + 1];
        int4 c = p[3 * q + 2];
        int b0 = ((a.x >> 5) << 6) | ((a.y >> 5) << 3) | (a.z >> 5);
        int b1 = ((a.w >> 5) << 6) | ((b.x >> 5) << 3) | (b.y >> 5);
        int b2 = ((b.z >> 5) << 6) | ((b.w >> 5) << 3) | (c.x >> 5);
        int b3 = ((c.y >> 5) << 6) | ((c.z >> 5) << 3) | (c.w >> 5);
        atomicAdd(&myh[b0], 1);
        atomicAdd(&myh[b1], 1);
        atomicAdd(&myh[b2], 1);
        atomicAdd(&myh[b3], 1);
    }
    __syncthreads();

    float h0 = (float)(hists[tid] + hists[520 + tid] + hists[1040 + tid] + hists[1560 + tid]);
    float h1 = (float)(hists[tid + 256] + hists[520 + tid + 256] +
                       hists[1040 + tid + 256] + hists[1560 + tid + 256]);
    float s = h0 * h0 + h1 * h1;
#pragma unroll
    for (int o = 16; o > 0; o >>= 1) s += __shfl_xor_sync(0xffffffffu, s, o);
    if ((tid & 31) == 0) wsum[tid >> 5] = s;
    __syncthreads();

    float tot = 0.f;
#pragma unroll
    for (int w = 0; w < 8; w++) tot += wsum[w];
    float rn = rsqrtf(tot);   // tot >= HW^2/NBINS > 0

    float* o = g_hist + (size_t)f * NBINS;
    o[tid] = h0 * rn;
    o[tid + 256] = h1 * rn;
}

// ---------------------------------------------------------------------------
// Kernel 2: banded self-similarity via tf32 mma.sync (m16n8k8).
// Block = one 32-t tile; computes dense D[32 x 160] rectangle over K=512.
// smem: [row 0..159][k 0..63] fp32, stride 68 (conflict-free fragment LDS).
// A rows are smem rows 56..87 (the t rows). 8 warps = 2(m16) x 4(n40).
// cp.async double-buffered K stages. Epilogue scatters valid l = jr-tr-6.
// ---------------------------------------------------------------------------
__device__ __forceinline__ unsigned f2tf(float x) {
    unsigned r;
    asm("cvt.rna.tf32.f32 %0, %1;" : "=r"(r) : "f"(x));
    return r;
}

__global__ void band_kernel(void) {
    extern __shared__ __align__(16) float sm[];   // 2 * STAGE_WORDS

    const int blk = blockIdx.x;               // 0..127
    const int b = blk >> 5;
    const int tb = (blk & 31) * BTILE;
    const int j0 = tb - 56;
    const int tid = threadIdx.x;              // 256
    const int lane = tid & 31, warp = tid >> 5;
    const int wm = warp >> 2, wn = warp & 3;  // m-half, n-column

    const float* hb = g_hist + (size_t)b * (TT_TOT * NBINS);

    float acc[5][4];
#pragma unroll
    for (int nt = 0; nt < 5; nt++)
#pragma unroll
        for (int i = 0; i < 4; i++) acc[nt][i] = 0.f;

    // ---- stage loader: 160 rows x 16 float4 = 2560 cp.asyncs, 10 per thread.
    // Per-thread loader state hoisted: clamped source row pointer + size.
    const int lrow0 = tid >> 4;               // row advances by 16 per iter
    const int lc4 = tid & 15;
    unsigned sbase = (unsigned)__cvta_generic_to_shared(sm);

    const float* lsrc[10];
    int lsz[10];
    unsigned ldst[10];
#pragma unroll
    for (int it = 0; it < 10; ++it) {
        int row = lrow0 + it * 16;
        int j = j0 + row;
        int jc = j < 0 ? 0 : (j > 1023 ? 1023 : j);
        lsrc[it] = hb + (size_t)jc * NBINS + lc4 * 4;
        lsz[it] = ((unsigned)j < 1024u) ? 16 : 0;
        ldst[it] = sbase + (unsigned)(row * SSTRIDE + lc4 * 4) * 4u;
    }

#define LOAD_STAGE(s, buf)                                                        \
    {                                                                             \
        const int kb = (s) * KCH;                                                 \
        const unsigned boff = (buf) * (STAGE_WORDS * 4u);                         \
        _Pragma("unroll")                                                         \
        for (int it = 0; it < 10; ++it) {                                         \
            asm volatile("cp.async.cg.shared.global [%0], [%1], 16, %2;\n"        \
                         :: "r"(ldst[it] + boff), "l"(lsrc[it] + kb),             \
                            "r"(lsz[it]));                                        \
        }                                                                         \
        asm volatile("cp.async.commit_group;\n");                                 \
    }

    LOAD_STAGE(0, 0)

    for (int s = 0; s < NSTAGES; ++s) {
        if (s < NSTAGES - 1) LOAD_STAGE(s + 1, (s + 1) & 1)
        asm volatile("cp.async.wait_group 1;\n" ::: "memory");
        __syncthreads();

        const float* B = sm + (s & 1) * STAGE_WORDS;
        const float* Ab = B + (56 + wm * 16 + (lane >> 2)) * SSTRIDE + (lane & 3);
        const float* Bb = B + (wn * 40 + (lane >> 2)) * SSTRIDE + (lane & 3);

#pragma unroll
        for (int k8 = 0; k8 < KCH / 8; ++k8) {
            const int ko = k8 * 8;
            unsigned a0 = f2tf(Ab[ko]);
            unsigned a1 = f2tf(Ab[8 * SSTRIDE + ko]);
            unsigned a2 = f2tf(Ab[ko + 4]);
            unsigned a3 = f2tf(Ab[8 * SSTRIDE + ko + 4]);
#pragma unroll
            for (int nt = 0; nt < 5; ++nt) {
                unsigned b0 = f2tf(Bb[nt * 8 * SSTRIDE + ko]);
                unsigned b1 = f2tf(Bb[nt * 8 * SSTRIDE + ko + 4]);
                asm volatile(
                    "mma.sync.aligned.m16n8k8.row.col.f32.tf32.tf32.f32 "
                    "{%0,%1,%2,%3}, {%4,%5,%6,%7}, {%8,%9}, {%0,%1,%2,%3};\n"
                    : "+f"(acc[nt][0]), "+f"(acc[nt][1]),
                      "+f"(acc[nt][2]), "+f"(acc[nt][3])
                    : "r"(a0), "r"(a1), "r"(a2), "r"(a3), "r"(b0), "r"(b1));
            }
        }
        __syncthreads();
    }

    // ---- epilogue: D(tr, jr) -> win[t][l], l = jr - tr - 6
    const int tr0 = wm * 16 + (lane >> 2);
    float* wb = g_win + (size_t)b * (TT_TOT * LOOKUP);
#pragma unroll
    for (int nt = 0; nt < 5; ++nt) {
        int jr = wn * 40 + nt * 8 + 2 * (lane & 3);
#pragma unroll
        for (int half = 0; half < 2; ++half) {
            int tr = tr0 + half * 8;
            int t = tb + tr;
            float* wr = wb + (size_t)t * LOOKUP;
            int l = jr - tr - 6;
            if ((unsigned)l < (unsigned)LOOKUP) wr[l] = acc[nt][2 * half];
            if ((unsigned)(l + 1) < (unsigned)LOOKUP) wr[l + 1] = acc[nt][2 * half + 1];
        }
    }
}

// ---------------------------------------------------------------------------
// Kernel 3: out[bt, o] = relu(win[bt, :] @ W[:, o] + b[o])
// ---------------------------------------------------------------------------
__global__ void fc_kernel(const float* __restrict__ fcw,
                          const float* __restrict__ fcb,
                          float* __restrict__ out) {
    extern __shared__ __align__(16) float swt[];   // LOOKUP*OUT_DIM
    __shared__ float swin[RPB][LOOKUP + 3];

    const int tid = threadIdx.x;    // 128
    const int bt0 = blockIdx.x * RPB;

    for (int e = tid; e < LOOKUP * OUT_DIM; e += 128) swt[e] = fcw[e];
    for (int e = tid; e < RPB * LOOKUP; e += 128) {
        int row = e / LOOKUP;
        int l = e - row * LOOKUP;
        swin[row][l] = g_win[(size_t)(bt0 + row) * LOOKUP + l];
    }
    __syncthreads();

    float acc[RPB];
    float bias = fcb[tid];
#pragma unroll
    for (int r = 0; r < RPB; ++r) acc[r] = bias;

#pragma unroll 4
    for (int l = 0; l < LOOKUP; ++l) {
        float wv = swt[l * OUT_DIM + tid];
#pragma unroll
        for (int r = 0; r < RPB; ++r) acc[r] += swin[r][l] * wv;
    }

#pragma unroll
    for (int r = 0; r < RPB; ++r)
        out[(size_t)(bt0 + r) * OUT_DIM + tid] = fmaxf(acc[r], 0.f);
}

// ---------------------------------------------------------------------------
extern "C" void kernel_launch(void* const* d_in, const int* in_sizes, int n_in,
                              void* d_out, int out_size) {
    const int* frames = (const int*)d_in[0];
    const float* fcw = (const float*)d_in[1];
    const float* fcb = (const float*)d_in[2];
    float* out = (float*)d_out;

    cudaFuncSetAttribute(band_kernel, cudaFuncAttributeMaxDynamicSharedMemorySize,
                         2 * STAGE_WORDS * (int)sizeof(float));
    cudaFuncSetAttribute(fc_kernel, cudaFuncAttributeMaxDynamicSharedMemorySize,
                         LOOKUP * OUT_DIM * (int)sizeof(float));

    hist_kernel<<<BB * TT_TOT, 256>>>(frames);
    band_kernel<<<(BB * TT_TOT) / BTILE, 256, 2 * STAGE_WORDS * sizeof(float)>>>();
    fc_kernel<<<(BB * TT_TOT) / RPB, 128, LOOKUP * OUT_DIM * sizeof(float)>>>(fcw, fcb, out);
}

// round 14
// speedup vs baseline: 2.1626x; 1.4553x over previous
#include <cuda_runtime.h>

#define BB 4
#define TT_TOT 1024
#define HW 1296
#define NBINS 512
#define LOOKUP 101
#define OUT_DIM 128

// band kernel (tf32 mma)
#define BTILE 32
#define BROWS 160          // j in [tb-56, tb+104)
#define SSTRIDE 68         // floats per smem row (64 + 4 pad -> conflict-free frags)
#define KCH 64             // K per stage
#define NSTAGES 8          // 512 / 64
#define STAGE_WORDS (BROWS * SSTRIDE)
// fused fc smem layout (floats, after the 2 stage buffers)
#define SW_OFF   (2 * STAGE_WORDS)                 // W: 101*128
#define SB_OFF   (SW_OFF + LOOKUP * OUT_DIM)       // bias: 128
#define SWIN_OFF (SB_OFF + OUT_DIM)                // win: 32*104
#define WINP 104
#define SMEM_FLOATS (SWIN_OFF + BTILE * WINP)

__device__ float g_hist[BB * TT_TOT * NBINS];   // 8 MB tf32-rounded normalized hists

// ---------------------------------------------------------------------------
// Kernel 1: per-frame 512-bin color histogram + L2 normalize.
// Output is pre-rounded to tf32 (cvt.rna) so the band kernel's MMA can consume
// LDS results directly with no per-element cvt.
// ---------------------------------------------------------------------------
__global__ void hist_kernel(const int* __restrict__ frames) {
    __shared__ int hists[4 * 520];   // 4 copies, 520-int stride (8-bank stagger)
    __shared__ float wsum[8];
    const int f = blockIdx.x;
    const int tid = threadIdx.x;     // 256

    for (int i = tid; i < 4 * 520; i += 256) hists[i] = 0;
    __syncthreads();

    const int4* p = (const int4*)frames + (size_t)f * (HW * 3 / 4);
    int* myh = hists + (tid & 3) * 520;

    for (int q = tid; q < HW / 4; q += 256) {
        int4 a = p[3 * q + 0];
        int4 b = p[3 * q + 1];
        int4 c = p[3 * q + 2];
        int b0 = ((a.x >> 5) << 6) | ((a.y >> 5) << 3) | (a.z >> 5);
        int b1 = ((a.w >> 5) << 6) | ((b.x >> 5) << 3) | (b.y >> 5);
        int b2 = ((b.z >> 5) << 6) | ((b.w >> 5) << 3) | (c.x >> 5);
        int b3 = ((c.y >> 5) << 6) | ((c.z >> 5) << 3) | (c.w >> 5);
        atomicAdd(&myh[b0], 1);
        atomicAdd(&myh[b1], 1);
        atomicAdd(&myh[b2], 1);
        atomicAdd(&myh[b3], 1);
    }
    __syncthreads();

    float h0 = (float)(hists[tid] + hists[520 + tid] + hists[1040 + tid] + hists[1560 + tid]);
    float h1 = (float)(hists[tid + 256] + hists[520 + tid + 256] +
                       hists[1040 + tid + 256] + hists[1560 + tid + 256]);
    float s = h0 * h0 + h1 * h1;
#pragma unroll
    for (int o = 16; o > 0; o >>= 1) s += __shfl_xor_sync(0xffffffffu, s, o);
    if ((tid & 31) == 0) wsum[tid >> 5] = s;
    __syncthreads();

    float tot = 0.f;
#pragma unroll
    for (int w = 0; w < 8; w++) tot += wsum[w];
    float rn = rsqrtf(tot);   // tot >= HW^2/NBINS > 0

    unsigned u0, u1;
    asm("cvt.rna.tf32.f32 %0, %1;" : "=r"(u0) : "f"(h0 * rn));
    asm("cvt.rna.tf32.f32 %0, %1;" : "=r"(u1) : "f"(h1 * rn));
    float* o = g_hist + (size_t)f * NBINS;
    o[tid] = __uint_as_float(u0);
    o[tid + 256] = __uint_as_float(u1);
}

// ---------------------------------------------------------------------------
// Kernel 2: banded self-similarity via tf32 mma.sync (m16n8k8) + FUSED FC.
// Block = one 32-t tile; dense D[32 x 160] over K=512, cp.async double-buffered.
// Epilogue scatters the valid 101-wide window into smem, then the block
// computes out[32 x 128] = relu(win @ W + b) in fp32 (W/b staged in smem).
// ---------------------------------------------------------------------------
__global__ void band_kernel(const float* __restrict__ fcw,
                            const float* __restrict__ fcb,
                            float* __restrict__ out) {
    extern __shared__ __align__(16) float sm[];   // SMEM_FLOATS

    const int blk = blockIdx.x;               // 0..127
    const int b = blk >> 5;
    const int tb = (blk & 31) * BTILE;
    const int j0 = tb - 56;
    const int tid = threadIdx.x;              // 256
    const int lane = tid & 31, warp = tid >> 5;
    const int wm = warp >> 2, wn = warp & 3;  // m-half, n-column

    const float* hb = g_hist + (size_t)b * (TT_TOT * NBINS);

    float acc[5][4];
#pragma unroll
    for (int nt = 0; nt < 5; nt++)
#pragma unroll
        for (int i = 0; i < 4; i++) acc[nt][i] = 0.f;

    // ---- stage loader: 160 rows x 16 float4 = 2560 cp.asyncs, 10 per thread.
    const int lrow0 = tid >> 4;
    const int lc4 = tid & 15;
    unsigned sbase = (unsigned)__cvta_generic_to_shared(sm);

    const float* lsrc[10];
    int lsz[10];
    unsigned ldst[10];
#pragma unroll
    for (int it = 0; it < 10; ++it) {
        int row = lrow0 + it * 16;
        int j = j0 + row;
        int jc = j < 0 ? 0 : (j > 1023 ? 1023 : j);
        lsrc[it] = hb + (size_t)jc * NBINS + lc4 * 4;
        lsz[it] = ((unsigned)j < 1024u) ? 16 : 0;
        ldst[it] = sbase + (unsigned)(row * SSTRIDE + lc4 * 4) * 4u;
    }

#define LOAD_STAGE(s, buf)                                                        \
    {                                                                             \
        const int kb = (s) * KCH;                                                 \
        const unsigned boff = (buf) * (STAGE_WORDS * 4u);                         \
        _Pragma("unroll")                                                         \
        for (int it = 0; it < 10; ++it) {                                         \
            asm volatile("cp.async.cg.shared.global [%0], [%1], 16, %2;\n"        \
                         :: "r"(ldst[it] + boff), "l"(lsrc[it] + kb),             \
                            "r"(lsz[it]));                                        \
        }                                                                         \
        asm volatile("cp.async.commit_group;\n");                                 \
    }

    LOAD_STAGE(0, 0)

    // Stage FC weights/bias into smem (L2-resident after first wave); overlaps
    // with the stage-0 cp.async in flight.
    for (int e = tid; e < LOOKUP * OUT_DIM; e += 256) sm[SW_OFF + e] = fcw[e];
    if (tid < OUT_DIM) sm[SB_OFF + tid] = fcb[tid];

    for (int s = 0; s < NSTAGES; ++s) {
        if (s < NSTAGES - 1) LOAD_STAGE(s + 1, (s + 1) & 1)
        asm volatile("cp.async.wait_group 1;\n" ::: "memory");
        __syncthreads();

        const float* B = sm + (s & 1) * STAGE_WORDS;
        const float* Ab = B + (56 + wm * 16 + (lane >> 2)) * SSTRIDE + (lane & 3);
        const float* Bb = B + (wn * 40 + (lane >> 2)) * SSTRIDE + (lane & 3);

#pragma unroll
        for (int k8 = 0; k8 < KCH / 8; ++k8) {
            const int ko = k8 * 8;
            unsigned a0 = __float_as_uint(Ab[ko]);
            unsigned a1 = __float_as_uint(Ab[8 * SSTRIDE + ko]);
            unsigned a2 = __float_as_uint(Ab[ko + 4]);
            unsigned a3 = __float_as_uint(Ab[8 * SSTRIDE + ko + 4]);
#pragma unroll
            for (int nt = 0; nt < 5; ++nt) {
                unsigned b0 = __float_as_uint(Bb[nt * 8 * SSTRIDE + ko]);
                unsigned b1 = __float_as_uint(Bb[nt * 8 * SSTRIDE + ko + 4]);
                asm volatile(
                    "mma.sync.aligned.m16n8k8.row.col.f32.tf32.tf32.f32 "
                    "{%0,%1,%2,%3}, {%4,%5,%6,%7}, {%8,%9}, {%0,%1,%2,%3};\n"
                    : "+f"(acc[nt][0]), "+f"(acc[nt][1]),
                      "+f"(acc[nt][2]), "+f"(acc[nt][3])
                    : "r"(a0), "r"(a1), "r"(a2), "r"(a3), "r"(b0), "r"(b1));
            }
        }
        __syncthreads();
    }

    // ---- epilogue 1: scatter D(tr, jr) -> swin[tr][l], l = jr - tr - 6.
    // Every (tr, l) pair with l in [0,101) has exactly one source (jr = tr+l+6).
    {
        float* swin = sm + SWIN_OFF;
        const int tr0 = wm * 16 + (lane >> 2);
#pragma unroll
        for (int nt = 0; nt < 5; ++nt) {
            int jr = wn * 40 + nt * 8 + 2 * (lane & 3);
#pragma unroll
            for (int half = 0; half < 2; ++half) {
                int tr = tr0 + half * 8;
                int l = jr - tr - 6;
                if ((unsigned)l < (unsigned)LOOKUP)
                    swin[tr * WINP + l] = acc[nt][2 * half];
                if ((unsigned)(l + 1) < (unsigned)LOOKUP)
                    swin[tr * WINP + l + 1] = acc[nt][2 * half + 1];
            }
        }
    }
    __syncthreads();

    // ---- epilogue 2: fused FC. Warp w handles t rows 4w..4w+3; lane owns
    // output cols 4*lane..4*lane+3.
    {
        const float* sW = sm + SW_OFF;
        const float* swin = sm + SWIN_OFF;
        float4 bias = *(const float4*)(sm + SB_OFF + 4 * lane);

        float f[4][4];
#pragma unroll
        for (int r = 0; r < 4; ++r) {
            f[r][0] = bias.x; f[r][1] = bias.y; f[r][2] = bias.z; f[r][3] = bias.w;
        }

#pragma unroll 4
        for (int l = 0; l < LOOKUP; ++l) {
            float4 wv = *(const float4*)(sW + l * OUT_DIM + 4 * lane);
#pragma unroll
            for (int r = 0; r < 4; ++r) {
                float sv = swin[(4 * warp + r) * WINP + l];
                f[r][0] += sv * wv.x;
                f[r][1] += sv * wv.y;
                f[r][2] += sv * wv.z;
                f[r][3] += sv * wv.w;
            }
        }

#pragma unroll
        for (int r = 0; r < 4; ++r) {
            int t = tb + 4 * warp + r;
            float4 o;
            o.x = fmaxf(f[r][0], 0.f);
            o.y = fmaxf(f[r][1], 0.f);
            o.z = fmaxf(f[r][2], 0.f);
            o.w = fmaxf(f[r][3], 0.f);
            *(float4*)(out + ((size_t)(b * TT_TOT + t)) * OUT_DIM + 4 * lane) = o;
        }
    }
}

// ---------------------------------------------------------------------------
extern "C" void kernel_launch(void* const* d_in, const int* in_sizes, int n_in,
                              void* d_out, int out_size) {
    const int* frames = (const int*)d_in[0];
    const float* fcw = (const float*)d_in[1];
    const float* fcb = (const float*)d_in[2];
    float* out = (float*)d_out;

    cudaFuncSetAttribute(band_kernel, cudaFuncAttributeMaxDynamicSharedMemorySize,
                         SMEM_FLOATS * (int)sizeof(float));

    hist_kernel<<<BB * TT_TOT, 256>>>(frames);
    band_kernel<<<(BB * TT_TOT) / BTILE, 256, SMEM_FLOATS * sizeof(float)>>>(fcw, fcb, out);
}